// round 16
// baseline (speedup 1.0000x reference)
#include <cuda_runtime.h>
#include <cuda_bf16.h>
#include <cstdint>
#include <cstddef>

// Problem constants
constexpr int PB = 8, PS = 1024, PD = 768, PH = 12, PHD = 64;
constexpr size_t QKV_ELEMS = (size_t)PB * PH * PS * PHD;        // 6,291,456
constexpr size_t OUT_ELEMS = (size_t)PB * PS * PD;              // 6,291,456
constexpr size_t XE = (size_t)PB * PS * PD;                     // per matrix
constexpr size_t WE = (size_t)PD * PD;                          // per matrix
constexpr size_t RELP_ELEMS = (size_t)PB * PS * PS;             // 8,388,608

// Scratch (no allocations allowed -> __device__ globals)
__device__ __nv_bfloat16 g_xhi[3 * XE];
__device__ __nv_bfloat16 g_xlo[3 * XE];
__device__ __nv_bfloat16 g_whi[3 * WE];
__device__ __nv_bfloat16 g_wlo[3 * WE];
__device__ __nv_bfloat16 g_qhi[QKV_ELEMS], g_qlo[QKV_ELEMS];
__device__ __nv_bfloat16 g_khi[QKV_ELEMS], g_klo[QKV_ELEMS];
__device__ __nv_bfloat16 g_vhi[QKV_ELEMS], g_vlo[QKV_ELEMS];
__device__ __nv_bfloat16 g_vthi[QKV_ELEMS], g_vtlo[QKV_ELEMS];   // [b][h][hd][s]
__device__ float g_relp[RELP_ELEMS];
__device__ uint32_t g_maskbits[RELP_ELEMS / 32];                 // 1MB packed mask
__device__ float g_psum[(size_t)PB * PH * PS * 8];               // per-CTA row partial sums
__device__ int   g_mask_mode;   // 0 = uint8/bool, 1 = int32, 2 = float32

// ---------------------------------------------------------------------------
// Tensor-core + async-copy helpers
// ---------------------------------------------------------------------------
__device__ __forceinline__ uint32_t smem_to_u32(const void* p) {
    uint32_t a;
    asm("{ .reg .u64 t; cvta.to.shared.u64 t, %1; cvt.u32.u64 %0, t; }" : "=r"(a) : "l"(p));
    return a;
}
__device__ __forceinline__ void ldmx4(uint32_t* r, uint32_t addr) {
    asm volatile("ldmatrix.sync.aligned.m8n8.x4.shared.b16 {%0,%1,%2,%3}, [%4];"
        : "=r"(r[0]), "=r"(r[1]), "=r"(r[2]), "=r"(r[3]) : "r"(addr));
}
__device__ __forceinline__ void mma16816(float* c, const uint32_t* a, uint32_t b0, uint32_t b1) {
    asm volatile("mma.sync.aligned.m16n8k16.row.col.f32.bf16.bf16.f32 "
        "{%0,%1,%2,%3}, {%4,%5,%6,%7}, {%8,%9}, {%0,%1,%2,%3};"
        : "+f"(c[0]), "+f"(c[1]), "+f"(c[2]), "+f"(c[3])
        : "r"(a[0]), "r"(a[1]), "r"(a[2]), "r"(a[3]), "r"(b0), "r"(b1));
}
__device__ __forceinline__ void cp_async16(uint32_t dst, const void* src) {
    asm volatile("cp.async.cg.shared.global [%0], [%1], 16;" :: "r"(dst), "l"(src));
}
__device__ __forceinline__ void cp_commit() {
    asm volatile("cp.async.commit_group;" ::: "memory");
}
template <int N>
__device__ __forceinline__ void cp_wait() {
    asm volatile("cp.async.wait_group %0;" :: "n"(N) : "memory");
}
#define SWZ128(off) ((off) ^ (((off) >> 3) & 0x70))

// ---------------------------------------------------------------------------
// Mask dtype probe (deterministic)
// ---------------------------------------------------------------------------
__global__ void detect_mask_kernel(const void* __restrict__ mask) {
    __shared__ int sawFloat, sawOther;
    if (threadIdx.x == 0) { sawFloat = 0; sawOther = 0; }
    __syncthreads();
    const unsigned int* w = (const unsigned int*)mask;
    int lf = 0, lo = 0;
    for (int i = threadIdx.x; i < 2048; i += blockDim.x) {
        unsigned int x = w[i];
        if (x == 0x3F800000u) lf = 1;
        else if (x > 1u) lo = 1;
    }
    if (lf) atomicOr(&sawFloat, 1);
    if (lo) atomicOr(&sawOther, 1);
    __syncthreads();
    if (threadIdx.x == 0) g_mask_mode = sawFloat ? 2 : (sawOther ? 0 : 1);
}

__device__ __forceinline__ bool read_mask(const void* m, size_t idx, int mode) {
    if (mode == 0) return ((const unsigned char*)m)[idx] != 0;
    if (mode == 1) return ((const int*)m)[idx] != 0;
    return ((const float*)m)[idx] != 0.0f;
}

// ---------------------------------------------------------------------------
// Conversion kernels: fp32 -> (bf16 hi, bf16 lo) split
// ---------------------------------------------------------------------------
__global__ void conv_x_kernel(const float* __restrict__ q, const float* __restrict__ k,
                              const float* __restrict__ v) {
    const int z = blockIdx.y;
    const float* src = (z == 0) ? q : (z == 1) ? k : v;
    __nv_bfloat16* hi = g_xhi + (size_t)z * XE;
    __nv_bfloat16* lo = g_xlo + (size_t)z * XE;
    const size_t i2 = ((size_t)blockIdx.x * blockDim.x + threadIdx.x) * 2;
    if (i2 + 1 >= XE) return;
    const float2 s = *(const float2*)(src + i2);
    const __nv_bfloat16 h0 = __float2bfloat16_rn(s.x);
    const __nv_bfloat16 h1 = __float2bfloat16_rn(s.y);
    *(__nv_bfloat162*)(hi + i2) = __halves2bfloat162(h0, h1);
    *(__nv_bfloat162*)(lo + i2) = __floats2bfloat162_rn(
        s.x - __bfloat162float(h0), s.y - __bfloat162float(h1));
}

__global__ void conv_w_kernel(const float* __restrict__ wq, const float* __restrict__ wk,
                              const float* __restrict__ wv) {
    const int z = blockIdx.y;
    const float* src = (z == 0) ? wq : (z == 1) ? wk : wv;
    __nv_bfloat16* hi = g_whi + (size_t)z * WE;
    __nv_bfloat16* lo = g_wlo + (size_t)z * WE;
    const size_t i2 = ((size_t)blockIdx.x * blockDim.x + threadIdx.x) * 2;
    if (i2 + 1 >= WE) return;
    const float2 s = *(const float2*)(src + i2);
    const __nv_bfloat16 h0 = __float2bfloat16_rn(s.x);
    const __nv_bfloat16 h1 = __float2bfloat16_rn(s.y);
    *(__nv_bfloat162*)(hi + i2) = __halves2bfloat162(h0, h1);
    *(__nv_bfloat162*)(lo + i2) = __floats2bfloat162_rn(
        s.x - __bfloat162float(h0), s.y - __bfloat162float(h1));
}

// ---------------------------------------------------------------------------
// relp kernel: rel_attn softmax per row + pack mask to bitmask.
// Loads hoisted ahead of ballots to keep MLP high.
// ---------------------------------------------------------------------------
__global__ void relp_kernel(const float* __restrict__ rel, const void* __restrict__ mask) {
    const int lane = threadIdx.x & 31;
    const int warp = threadIdx.x >> 5;
    const int row = blockIdx.x * 8 + warp;          // 0..8191 = b*1024+s
    const size_t rbase = (size_t)row * PS;
    const int mmode = g_mask_mode;
    float vals[32];
    uint32_t mybits = 0;
    float mx = -3.0e38f;
#pragma unroll
    for (int i = 0; i < 32; i++) {
        const int c = lane + i * 32;
        const bool m = read_mask(mask, rbase + c, mmode);
        mybits |= (uint32_t)m << i;
        const float v = rel[rbase + c];
        const float relm = m ? v : 0.0f;
        const float logit = (relm == 0.0f) ? -10000.0f : relm;
        vals[i] = logit;
        mx = fmaxf(mx, logit);
    }
    uint32_t myword = 0;
#pragma unroll
    for (int i = 0; i < 32; i++) {
        const uint32_t w = __ballot_sync(0xffffffffu, (mybits >> i) & 1u);
        if (lane == i) myword = w;
    }
    g_maskbits[(size_t)row * 32 + lane] = myword;
#pragma unroll
    for (int o = 16; o; o >>= 1) mx = fmaxf(mx, __shfl_xor_sync(0xffffffffu, mx, o));
    float sum = 0.0f;
#pragma unroll
    for (int i = 0; i < 32; i++) { vals[i] = __expf(vals[i] - mx); sum += vals[i]; }
#pragma unroll
    for (int o = 16; o; o >>= 1) sum += __shfl_xor_sync(0xffffffffu, sum, o);
    const float inv = 1.0f / sum;
#pragma unroll
    for (int i = 0; i < 32; i++) g_relp[rbase + lane + i * 32] = vals[i] * inv;
}

// ---------------------------------------------------------------------------
// Kernel 1: HMMA bf16-split projection GEMM, cp.async 2-stage pipeline.
// ---------------------------------------------------------------------------
constexpr int PROJ_SMEM = 2 * 65536;

__device__ __forceinline__ void load_slab_async(const __nv_bfloat16* __restrict__ src,
                                                int row0, int k0, uint32_t dstu, int tid) {
#pragma unroll
    for (int it = 0; it < 4; it++) {
        const int c = tid + it * 256;          // 0..1023 16B-chunks
        const int r = c >> 3;                  // 0..127
        const int e8 = (c & 7) * 8;
        cp_async16(dstu + SWZ128(r * 128 + e8 * 2),
                   src + (size_t)(row0 + r) * PD + k0 + e8);
    }
}

// Load a [128 x 64] bf16 tile with contiguous 128B rows.
__device__ __forceinline__ void load_tile64(const __nv_bfloat16* __restrict__ src,
                                            size_t base, char* dst, int tid) {
#pragma unroll
    for (int it = 0; it < 4; it++) {
        const int c = tid + it * 256;
        const int r = c >> 3;
        const int e8 = (c & 7) * 8;
        const uint4 v = *(const uint4*)(src + base + (size_t)r * 64 + e8);
        *(uint4*)(dst + SWZ128(r * 128 + e8 * 2)) = v;
    }
}

__global__ __launch_bounds__(256, 1)
void proj_mma_kernel(const float* __restrict__ bq, const float* __restrict__ bk,
                     const float* __restrict__ bv)
{
    extern __shared__ char sm[];
    __shared__ float bias_s[128];

    const int tid  = threadIdx.x;
    const int warp = tid >> 5;
    const int lane = tid & 31;
    const int wm = warp >> 2;
    const int wn = warp & 3;
    const int z  = blockIdx.z;
    const int n0 = blockIdx.x * 128;
    const int m0 = blockIdx.y * 128;

    const __nv_bfloat16* xhi = g_xhi + (size_t)z * XE;
    const __nv_bfloat16* xlo = g_xlo + (size_t)z * XE;
    const __nv_bfloat16* whi = g_whi + (size_t)z * WE;
    const __nv_bfloat16* wlo = g_wlo + (size_t)z * WE;
    const float* bias = (z == 0) ? bq : (z == 1) ? bk : bv;
    __nv_bfloat16* ohi = (z == 0) ? g_qhi : (z == 1) ? g_khi : g_vhi;
    __nv_bfloat16* olo = (z == 0) ? g_qlo : (z == 1) ? g_klo : g_vlo;

    if (tid < 128) bias_s[tid] = bias[n0 + tid];

    const uint32_t ubase = smem_to_u32(sm);

    float acc[4][4][4];
#pragma unroll
    for (int i = 0; i < 4; i++)
#pragma unroll
        for (int j = 0; j < 4; j++)
#pragma unroll
            for (int c = 0; c < 4; c++) acc[i][j][c] = 0.0f;

    const int lrow  = lane & 15;
    const int lcolb = (lane >> 4) * 16;

    {
        const uint32_t du = ubase;
        load_slab_async(xhi, m0, 0, du,         tid);
        load_slab_async(xlo, m0, 0, du + 16384, tid);
        load_slab_async(whi, n0, 0, du + 32768, tid);
        load_slab_async(wlo, n0, 0, du + 49152, tid);
        cp_commit();
    }

    for (int s = 0; s < 12; s++) {
        if (s + 1 < 12) {
            const uint32_t du = ubase + ((s + 1) & 1) * 65536;
            const int k0 = (s + 1) * 64;
            load_slab_async(xhi, m0, k0, du,         tid);
            load_slab_async(xlo, m0, k0, du + 16384, tid);
            load_slab_async(whi, n0, k0, du + 32768, tid);
            load_slab_async(wlo, n0, k0, du + 49152, tid);
            cp_commit();
            cp_wait<1>();
        } else {
            cp_wait<0>();
        }
        __syncthreads();

        const uint32_t uAhi = ubase + (s & 1) * 65536;
        const uint32_t uAlo = uAhi + 16384;
        const uint32_t uBhi = uAhi + 32768;
        const uint32_t uBlo = uAhi + 49152;
#pragma unroll
        for (int ks = 0; ks < 4; ks++) {
            const int kb = ks * 32 + lcolb;
            uint32_t bhi[2][4], blo[2][4];
#pragma unroll
            for (int nt2 = 0; nt2 < 2; nt2++) {
                const int brow = wn * 32 + nt2 * 16 + lrow;
                ldmx4(bhi[nt2], uBhi + SWZ128(brow * 128 + kb));
                ldmx4(blo[nt2], uBlo + SWZ128(brow * 128 + kb));
            }
#pragma unroll
            for (int mt = 0; mt < 4; mt++) {
                const int arow = wm * 64 + mt * 16 + lrow;
                uint32_t a[4];
                ldmx4(a, uAhi + SWZ128(arow * 128 + kb));       // Ahi
#pragma unroll
                for (int nt2 = 0; nt2 < 2; nt2++)
#pragma unroll
                    for (int j = 0; j < 2; j++) {
                        mma16816(acc[mt][nt2 * 2 + j], a, bhi[nt2][j], bhi[nt2][2 + j]);
                        mma16816(acc[mt][nt2 * 2 + j], a, blo[nt2][j], blo[nt2][2 + j]);
                    }
                ldmx4(a, uAlo + SWZ128(arow * 128 + kb));       // Alo
#pragma unroll
                for (int nt2 = 0; nt2 < 2; nt2++)
#pragma unroll
                    for (int j = 0; j < 2; j++)
                        mma16816(acc[mt][nt2 * 2 + j], a, bhi[nt2][j], bhi[nt2][2 + j]);
            }
        }
        __syncthreads();
    }

    const int g   = lane >> 2;
    const int tg2 = (lane & 3) * 2;
#pragma unroll
    for (int mt = 0; mt < 4; mt++) {
#pragma unroll
        for (int nt = 0; nt < 4; nt++) {
            const int nc = wn * 32 + nt * 8 + tg2;
            const int n = n0 + nc;
            const int h = n >> 6, hd = n & 63;
            const int m = m0 + wm * 64 + mt * 16 + g;
            const int b = m >> 10, sq = m & 1023;
#pragma unroll
            for (int cc = 0; cc < 2; cc++) {
                const float y0 = acc[mt][nt][cc * 2 + 0] + bias_s[nc];
                const float y1 = acc[mt][nt][cc * 2 + 1] + bias_s[nc + 1];
                const __nv_bfloat16 h0 = __float2bfloat16_rn(y0);
                const __nv_bfloat16 h1 = __float2bfloat16_rn(y1);
                const size_t di = (((size_t)(b * PH + h)) * PS + sq + cc * 8) * PHD + hd;
                *(__nv_bfloat162*)(ohi + di) = __halves2bfloat162(h0, h1);
                *(__nv_bfloat162*)(olo + di) = __floats2bfloat162_rn(
                    y0 - __bfloat162float(h0), y1 - __bfloat162float(h1));
            }
        }
    }
}

// ---------------------------------------------------------------------------
// V transpose: [b][h][s][hd] -> [b][h][hd][s] (hi and lo)
// ---------------------------------------------------------------------------
__global__ void vtrans_kernel() {
    __shared__ __nv_bfloat16 th[64][65], tl[64][65];
    const int tid = threadIdx.x;
    const int bh = blockIdx.y;
    const int st = blockIdx.x * 64;
    const size_t src0 = ((size_t)bh * PS + st) * PHD;
#pragma unroll
    for (int it = 0; it < 16; it++) {
        const int i = tid + it * 256;
        const int s = i >> 6, hd = i & 63;
        th[hd][s] = g_vhi[src0 + (size_t)s * PHD + hd];
        tl[hd][s] = g_vlo[src0 + (size_t)s * PHD + hd];
    }
    __syncthreads();
    const size_t dst0 = (size_t)bh * PHD * PS + st;
#pragma unroll
    for (int it = 0; it < 16; it++) {
        const int i = tid + it * 256;
        const int hd = i >> 6, s = i & 63;
        g_vthi[dst0 + (size_t)hd * PS + s] = th[hd][s];
        g_vtlo[dst0 + (size_t)hd * PS + s] = tl[hd][s];
    }
}

// ---------------------------------------------------------------------------
// Kernel 2: scores GEMM + masked exp + per-CTA row sums.
// Writes p = mask ? 0 : exp(score/8) to prob, partial row sums to g_psum.
// (No max subtraction: |score/8| <~ 5 so exp is safe.)
// ---------------------------------------------------------------------------
constexpr int SG_SMEM = 4 * 16384;

__global__ __launch_bounds__(256, 2)
void scores_gemm_kernel(float* __restrict__ prob)
{
    extern __shared__ char sm4[];
    __shared__ float psum_s[128][4];
    char* Qhi_s = sm4;
    char* Qlo_s = sm4 + 16384;
    char* Khi_s = sm4 + 32768;
    char* Klo_s = sm4 + 49152;
    const uint32_t uQhi = smem_to_u32(Qhi_s);
    const uint32_t uQlo = smem_to_u32(Qlo_s);
    const uint32_t uKhi = smem_to_u32(Khi_s);
    const uint32_t uKlo = smem_to_u32(Klo_s);

    const int tid  = threadIdx.x;
    const int warp = tid >> 5;
    const int lane = tid & 31;
    const int wm = warp >> 2;
    const int wn = warp & 3;
    const int bh = blockIdx.z;
    const int b  = bh / PH;
    const int q0 = blockIdx.y * 128;
    const int k0 = blockIdx.x * 128;

    const size_t qb = ((size_t)bh * PS + q0) * PHD;
    const size_t kb0 = ((size_t)bh * PS + k0) * PHD;

    load_tile64(g_qhi, qb, Qhi_s, tid);
    load_tile64(g_qlo, qb, Qlo_s, tid);
    load_tile64(g_khi, kb0, Khi_s, tid);
    load_tile64(g_klo, kb0, Klo_s, tid);
    __syncthreads();

    float acc[4][4][4];
#pragma unroll
    for (int i = 0; i < 4; i++)
#pragma unroll
        for (int j = 0; j < 4; j++)
#pragma unroll
            for (int c = 0; c < 4; c++) acc[i][j][c] = 0.0f;

    const int lrow  = lane & 15;
    const int lcolb = (lane >> 4) * 16;

#pragma unroll
    for (int ks = 0; ks < 4; ks++) {
        const int kb = ks * 32 + lcolb;
        uint32_t bhi[2][4], blo[2][4];
#pragma unroll
        for (int nt2 = 0; nt2 < 2; nt2++) {
            const int brow = wn * 32 + nt2 * 16 + lrow;
            ldmx4(bhi[nt2], uKhi + SWZ128(brow * 128 + kb));
            ldmx4(blo[nt2], uKlo + SWZ128(brow * 128 + kb));
        }
#pragma unroll
        for (int mt = 0; mt < 4; mt++) {
            const int arow = wm * 64 + mt * 16 + lrow;
            uint32_t a[4];
            ldmx4(a, uQhi + SWZ128(arow * 128 + kb));       // Qhi
#pragma unroll
            for (int nt2 = 0; nt2 < 2; nt2++)
#pragma unroll
                for (int j = 0; j < 2; j++) {
                    mma16816(acc[mt][nt2 * 2 + j], a, bhi[nt2][j], bhi[nt2][2 + j]);
                    mma16816(acc[mt][nt2 * 2 + j], a, blo[nt2][j], blo[nt2][2 + j]);
                }
            ldmx4(a, uQlo + SWZ128(arow * 128 + kb));       // Qlo
#pragma unroll
            for (int nt2 = 0; nt2 < 2; nt2++)
#pragma unroll
                for (int j = 0; j < 2; j++)
                    mma16816(acc[mt][nt2 * 2 + j], a, bhi[nt2][j], bhi[nt2][2 + j]);
        }
    }

    // Epilogue: p = mask ? 0 : exp(score/8); write; per-row partial sums.
    const int g   = lane >> 2;
    const int tg2 = (lane & 3) * 2;
    const size_t pb = (size_t)bh * PS * PS;
    const int word = (k0 + wn * 32) >> 5;   // one 32-col word covers this warp's cols
#pragma unroll
    for (int mt = 0; mt < 4; mt++) {
        const int r0 = q0 + wm * 64 + mt * 16 + g;
        const int r1 = r0 + 8;
        const uint32_t w0b = g_maskbits[((size_t)b * PS + r0) * 32 + word];
        const uint32_t w1b = g_maskbits[((size_t)b * PS + r1) * 32 + word];
        float s0 = 0.0f, s1 = 0.0f;
#pragma unroll
        for (int nt = 0; nt < 4; nt++) {
            const int kcol = k0 + wn * 32 + nt * 8 + tg2;
            const int bit = kcol & 31;
            const float p00 = ((w0b >> bit)       & 1u) ? 0.0f : __expf(acc[mt][nt][0] * 0.125f);
            const float p01 = ((w0b >> (bit + 1)) & 1u) ? 0.0f : __expf(acc[mt][nt][1] * 0.125f);
            const float p10 = ((w1b >> bit)       & 1u) ? 0.0f : __expf(acc[mt][nt][2] * 0.125f);
            const float p11 = ((w1b >> (bit + 1)) & 1u) ? 0.0f : __expf(acc[mt][nt][3] * 0.125f);
            float2 v0, v1;
            v0.x = p00; v0.y = p01;
            v1.x = p10; v1.y = p11;
            *(float2*)(prob + pb + (size_t)r0 * PS + kcol) = v0;
            *(float2*)(prob + pb + (size_t)r1 * PS + kcol) = v1;
            s0 += p00 + p01;
            s1 += p10 + p11;
        }
        // reduce over the quad (4 lanes sharing the row)
        s0 += __shfl_xor_sync(0xffffffffu, s0, 1);
        s0 += __shfl_xor_sync(0xffffffffu, s0, 2);
        s1 += __shfl_xor_sync(0xffffffffu, s1, 1);
        s1 += __shfl_xor_sync(0xffffffffu, s1, 2);
        if ((lane & 3) == 0) {
            psum_s[wm * 64 + mt * 16 + g][wn]     = s0;
            psum_s[wm * 64 + mt * 16 + g + 8][wn] = s1;
        }
    }
    __syncthreads();
    if (tid < 128) {
        const float s = psum_s[tid][0] + psum_s[tid][1] + psum_s[tid][2] + psum_s[tid][3];
        g_psum[((size_t)bh * PS + q0 + tid) * 8 + blockIdx.x] = s;
    }
}

// ---------------------------------------------------------------------------
// Kernel 3: HMMA pv with fused combine. 2-stage pipeline (96KB, occ 2).
// Prologue: winv[q] = (1-l1)/rowsum. Convert phase: final = p*winv + l1*relp,
// writes final prob to gmem AND bf16 hi/lo to smem for the MMA.
// ---------------------------------------------------------------------------
constexpr int PV_SMEM = 2 * 49152;

__global__ __launch_bounds__(256, 2)
void pv_mma_kernel(const float* __restrict__ l1p, float* __restrict__ prob,
                   float* __restrict__ outp)
{
    extern __shared__ char sm3[];
    __shared__ float winv_s[128];
    const uint32_t ubase = smem_to_u32(sm3);

    const int tid  = threadIdx.x;
    const int warp = tid >> 5;
    const int lane = tid & 31;
    const int wm = warp >> 1;          // 0..3 (32 q rows)
    const int wn = warp & 1;           // 0..1 (32 hd cols)
    const int bh = blockIdx.y;
    const int b = bh / PH, h = bh % PH;
    const int q0 = blockIdx.x * 128;
    const float l1 = *l1p;
    const float w0 = 1.0f - l1;

    // winv per row (deterministic fixed-order sum of the 8 partials)
    if (tid < 128) {
        const float* ps = g_psum + ((size_t)bh * PS + q0 + tid) * 8;
        float s = ps[0] + ps[1] + ps[2] + ps[3] + ps[4] + ps[5] + ps[6] + ps[7];
        winv_s[tid] = w0 / s;
    }
    __syncthreads();

    const size_t pbase = ((size_t)bh * PS + q0) * PS;
    const size_t rbase = ((size_t)b * PS + q0) * PS;
    const size_t vtb = (size_t)bh * PHD * PS;

    float acc[2][4][4];
#pragma unroll
    for (int i = 0; i < 2; i++)
#pragma unroll
        for (int j = 0; j < 4; j++)
#pragma unroll
            for (int c = 0; c < 4; c++) acc[i][j][c] = 0.0f;

    const int lrow  = lane & 15;
    const int lcolb = (lane >> 4) * 16;

    // convert one slab: final = p*winv + l1*relp; write gmem; bf16 split -> smem
    auto convert_slab = [&](int kc0, uint32_t stage_u) {
#pragma unroll
        for (int it = 0; it < 8; it++) {
            const int c = tid + it * 256;
            const int q = c >> 4, k4 = (c & 15) * 4;
            float4 v = *(const float4*)(prob + pbase + (size_t)q * PS + kc0 + k4);
            const float4 rv = *(const float4*)(g_relp + rbase + (size_t)q * PS + kc0 + k4);
            const float wi = winv_s[q];
            v.x = v.x * wi + l1 * rv.x;
            v.y = v.y * wi + l1 * rv.y;
            v.z = v.z * wi + l1 * rv.z;
            v.w = v.w * wi + l1 * rv.w;
            *(float4*)(prob + pbase + (size_t)q * PS + kc0 + k4) = v;   // final output
            const __nv_bfloat16 h0 = __float2bfloat16_rn(v.x);
            const __nv_bfloat16 h1 = __float2bfloat16_rn(v.y);
            const __nv_bfloat16 h2 = __float2bfloat16_rn(v.z);
            const __nv_bfloat16 h3 = __float2bfloat16_rn(v.w);
            __nv_bfloat162 hp01 = __halves2bfloat162(h0, h1);
            __nv_bfloat162 hp23 = __halves2bfloat162(h2, h3);
            __nv_bfloat162 lp01 = __floats2bfloat162_rn(v.x - __bfloat162float(h0),
                                                        v.y - __bfloat162float(h1));
            __nv_bfloat162 lp23 = __floats2bfloat162_rn(v.z - __bfloat162float(h2),
                                                        v.w - __bfloat162float(h3));
            uint2 hv, lv;
            hv.x = *reinterpret_cast<uint32_t*>(&hp01);
            hv.y = *reinterpret_cast<uint32_t*>(&hp23);
            lv.x = *reinterpret_cast<uint32_t*>(&lp01);
            lv.y = *reinterpret_cast<uint32_t*>(&lp23);
            asm volatile("st.shared.v2.b32 [%0], {%1, %2};"
                :: "r"(stage_u + SWZ128(q * 128 + k4 * 2)), "r"(hv.x), "r"(hv.y) : "memory");
            asm volatile("st.shared.v2.b32 [%0], {%1, %2};"
                :: "r"(stage_u + 16384 + SWZ128(q * 128 + k4 * 2)), "r"(lv.x), "r"(lv.y) : "memory");
        }
    };
    auto loadv_slab = [&](int kc0, uint32_t stage_u) {
#pragma unroll
        for (int it = 0; it < 2; it++) {
            const int c = tid + it * 256;
            const int r = c >> 3, e8 = (c & 7) * 8;
            cp_async16(stage_u + 32768 + SWZ128(r * 128 + e8 * 2),
                       g_vthi + vtb + (size_t)r * PS + kc0 + e8);
            cp_async16(stage_u + 40960 + SWZ128(r * 128 + e8 * 2),
                       g_vtlo + vtb + (size_t)r * PS + kc0 + e8);
        }
    };

    convert_slab(0, ubase);
    loadv_slab(0, ubase);
    cp_commit();

    for (int s = 0; s < 16; s++) {
        cp_wait<0>();
        __syncthreads();
        if (s + 1 < 16) {
            const uint32_t nxt = ubase + ((s + 1) & 1) * 49152;
            convert_slab((s + 1) * 64, nxt);
            loadv_slab((s + 1) * 64, nxt);
            cp_commit();
        }
        const uint32_t cur = ubase + (s & 1) * 49152;
        const uint32_t uPhi = cur, uPlo = cur + 16384;
        const uint32_t uVhi = cur + 32768, uVlo = cur + 40960;
#pragma unroll
        for (int ks = 0; ks < 4; ks++) {
            const int kb = ks * 32 + lcolb;
            uint32_t bhi[2][4], blo[2][4];
#pragma unroll
            for (int nt2 = 0; nt2 < 2; nt2++) {
                const int brow = wn * 32 + nt2 * 16 + lrow;
                ldmx4(bhi[nt2], uVhi + SWZ128(brow * 128 + kb));
                ldmx4(blo[nt2], uVlo + SWZ128(brow * 128 + kb));
            }
#pragma unroll
            for (int mt = 0; mt < 2; mt++) {
                const int arow = wm * 32 + mt * 16 + lrow;
                uint32_t a[4];
                ldmx4(a, uPhi + SWZ128(arow * 128 + kb));
#pragma unroll
                for (int nt2 = 0; nt2 < 2; nt2++)
#pragma unroll
                    for (int j = 0; j < 2; j++) {
                        mma16816(acc[mt][nt2 * 2 + j], a, bhi[nt2][j], bhi[nt2][2 + j]);
                        mma16816(acc[mt][nt2 * 2 + j], a, blo[nt2][j], blo[nt2][2 + j]);
                    }
                ldmx4(a, uPlo + SWZ128(arow * 128 + kb));
#pragma unroll
                for (int nt2 = 0; nt2 < 2; nt2++)
#pragma unroll
                    for (int j = 0; j < 2; j++)
                        mma16816(acc[mt][nt2 * 2 + j], a, bhi[nt2][j], bhi[nt2][2 + j]);
            }
        }
        __syncthreads();
    }
    // epilogue
    const int g   = lane >> 2;
    const int tg2 = (lane & 3) * 2;
#pragma unroll
    for (int mt = 0; mt < 2; mt++) {
#pragma unroll
        for (int nt = 0; nt < 4; nt++) {
            const int nc = wn * 32 + nt * 8 + tg2;
            const int m = q0 + wm * 32 + mt * 16 + g;
            float2 v0, v1;
            v0.x = acc[mt][nt][0]; v0.y = acc[mt][nt][1];
            v1.x = acc[mt][nt][2]; v1.y = acc[mt][nt][3];
            *(float2*)(outp + ((size_t)b * PS + m) * PD + h * PHD + nc)     = v0;
            *(float2*)(outp + ((size_t)b * PS + m + 8) * PD + h * PHD + nc) = v1;
        }
    }
}

// ---------------------------------------------------------------------------
extern "C" void kernel_launch(void* const* d_in, const int* in_sizes, int n_in,
                              void* d_out, int out_size) {
    const float* query = (const float*)d_in[0];
    const float* key   = (const float*)d_in[1];
    const float* value = (const float*)d_in[2];
    const float* rel   = (const float*)d_in[3];
    const void*  mask  = d_in[4];
    const float* l1    = (const float*)d_in[5];
    const float* Wq    = (const float*)d_in[6];
    const float* bq    = (const float*)d_in[7];
    const float* Wk    = (const float*)d_in[8];
    const float* bk    = (const float*)d_in[9];
    const float* Wv    = (const float*)d_in[10];
    const float* bv    = (const float*)d_in[11];

    float* outp = (float*)d_out;
    float* prob = outp + OUT_ELEMS;

    detect_mask_kernel<<<1, 256>>>(mask);

    conv_x_kernel<<<dim3((unsigned)(XE / 512), 3), 256>>>(query, key, value);
    conv_w_kernel<<<dim3((unsigned)(WE / 512), 3), 256>>>(Wq, Wk, Wv);
    relp_kernel<<<1024, 256>>>(rel, mask);   // also packs g_maskbits (scores needs it)

    cudaFuncSetAttribute(proj_mma_kernel,
                         cudaFuncAttributeMaxDynamicSharedMemorySize, PROJ_SMEM);
    dim3 g1(PD / 128, (PB * PS) / 128, 3);     // (6, 64, 3)
    proj_mma_kernel<<<g1, 256, PROJ_SMEM>>>(bq, bk, bv);

    vtrans_kernel<<<dim3(16, PB * PH), 256>>>();

    cudaFuncSetAttribute(scores_gemm_kernel,
                         cudaFuncAttributeMaxDynamicSharedMemorySize, SG_SMEM);
    dim3 g2(PS / 128, PS / 128, PB * PH);      // (8, 8, 96)
    scores_gemm_kernel<<<g2, 256, SG_SMEM>>>(prob);

    cudaFuncSetAttribute(pv_mma_kernel,
                         cudaFuncAttributeMaxDynamicSharedMemorySize, PV_SMEM);
    dim3 g3(PS / 128, PB * PH);                // (8, 96)
    pv_mma_kernel<<<g3, 256, PV_SMEM>>>(l1, prob, outp);
}